// round 7
// baseline (speedup 1.0000x reference)
#include <cuda_runtime.h>
#include <cuda_fp16.h>
#include <cstdint>

#define Bn 256
#define Tn 256
#define Hn 1024
#define G4 4096
#define Dn 409
#define KX 448            // D padded to 7*64
#define MXG 65536         // B*T
#define BM 64
#define BN 128
#define NT 16             // k-tiles of 64 over K=1024
#define NCTA 128

// ---------------- device scratch ----------------------------------------------
__device__ __align__(16) __half g_W[(size_t)G4 * Hn];       // 8 MB fp16(Whh) gate-interleaved
__device__ __align__(16) __half g_Wx[(size_t)G4 * KX];      // 3.7 MB fp16(Wih)
__device__ __align__(16) __half g_xh[(size_t)MXG * KX];     // 58.7 MB x hi
__device__ __align__(16) __half g_xl[(size_t)MXG * KX];     // 58.7 MB x lo
__device__ float g_xg[(size_t)MXG * G4];                    // 1 GiB
__device__ __align__(16) __half g_hhi[2][Bn * Hn];
__device__ __align__(16) __half g_hlo[2][Bn * Hn];
__device__ float g_c[Bn * Hn];
__device__ float g_bias[G4];
__device__ int g_bar;

// ---------------- PTX helpers ---------------------------------------------------
__device__ __forceinline__ uint32_t s2u(const void* p) {
    uint32_t a;
    asm("{ .reg .u64 t; cvta.to.shared.u64 t, %1; cvt.u32.u64 %0, t; }" : "=r"(a) : "l"(p));
    return a;
}
__device__ __forceinline__ void cp16(uint32_t dst, const void* src) {
    asm volatile("cp.async.cg.shared.global [%0], [%1], 16;" :: "r"(dst), "l"(src));
}
__device__ __forceinline__ void cp_commit() { asm volatile("cp.async.commit_group;"); }
__device__ __forceinline__ void cp_wait2() { asm volatile("cp.async.wait_group 2;" ::: "memory"); }

__device__ __forceinline__ void ldsm4(uint32_t& r0, uint32_t& r1, uint32_t& r2, uint32_t& r3,
                                      uint32_t addr) {
    asm volatile("ldmatrix.sync.aligned.m8n8.x4.shared.b16 {%0,%1,%2,%3}, [%4];"
                 : "=r"(r0), "=r"(r1), "=r"(r2), "=r"(r3) : "r"(addr));
}
__device__ __forceinline__ void mma16816(float* d, const uint32_t* a, uint32_t b0, uint32_t b1) {
    asm volatile(
        "mma.sync.aligned.m16n8k16.row.col.f32.f16.f16.f32 "
        "{%0,%1,%2,%3}, {%4,%5,%6,%7}, {%8,%9}, {%0,%1,%2,%3};"
        : "+f"(d[0]), "+f"(d[1]), "+f"(d[2]), "+f"(d[3])
        : "r"(a[0]), "r"(a[1]), "r"(a[2]), "r"(a[3]), "r"(b0), "r"(b1));
}

#define SW128(o) ((o) ^ (((o) >> 3) & 0x70))
// persistent recurrence stage: A_hi 8KB, A_lo 8KB, B 16KB
#define PST 32768
#define PSMEM (4 * PST)
// xg stage: A_hi 16KB @0, A_lo 16KB @16384, B 16KB @32768
#define XST 49152
#define XSMEM (3 * XST)

__device__ __forceinline__ float sigf(float x) { return 1.f / (1.f + expf(-x)); }

// ---------------- prep kernels --------------------------------------------------
__global__ void prep_x(const float* __restrict__ xt, const float* __restrict__ xa,
                       const float* __restrict__ xv) {
    size_t idx = (size_t)blockIdx.x * blockDim.x + threadIdx.x;
    if (idx >= (size_t)MXG * KX) return;
    int c = idx % KX;
    int r = idx / KX;             // r = t*256 + b
    int t = r >> 8, b = r & 255;
    int bt = b * Tn + t;
    float v = 0.f;
    if (c < 300)       v = xt[(size_t)bt * 300 + c];
    else if (c < 374)  v = xa[(size_t)bt * 74 + (c - 300)];
    else if (c < 409)  v = xv[(size_t)bt * 35 + (c - 374)];
    __half hi = __float2half_rn(v);
    g_xh[idx] = hi;
    g_xl[idx] = __float2half_rn(v - __half2float(hi));
}

__global__ void prep_w(const float* __restrict__ Whh) {
    size_t idx = (size_t)blockIdx.x * blockDim.x + threadIdx.x;
    if (idx >= (size_t)G4 * Hn) return;
    int c = idx % Hn;
    int rp = idx / Hn;
    int k = rp >> 2, g = rp & 3;
    g_W[idx] = __float2half_rn(Whh[(size_t)(g * Hn + k) * Hn + c]);
}

__global__ void prep_wx(const float* __restrict__ Wih) {
    size_t idx = (size_t)blockIdx.x * blockDim.x + threadIdx.x;
    if (idx >= (size_t)G4 * KX) return;
    int c = idx % KX;
    int rp = idx / KX;
    int k = rp >> 2, g = rp & 3;
    float v = (c < Dn) ? Wih[(size_t)(g * Hn + k) * Dn + c] : 0.f;
    g_Wx[idx] = __float2half_rn(v);
}

__global__ void prep_bias(const float* __restrict__ bih, const float* __restrict__ bhh) {
    int o = blockIdx.x * blockDim.x + threadIdx.x;
    if (o >= G4) return;
    int k = o >> 2, g = o & 3;
    g_bias[o] = bih[g * Hn + k] + bhh[g * Hn + k];
}

__global__ void init_state() {
    int idx = blockIdx.x * blockDim.x + threadIdx.x;
    if (idx == 0) g_bar = 0;
    if (idx < Bn * Hn) {
        g_hhi[0][idx] = __float2half_rn(0.f);
        g_hlo[0][idx] = __float2half_rn(0.f);
        g_c[idx] = 0.f;
    }
}

// ---------------- xg GEMM: g_xg = (x_hi + x_lo) @ fp16(Wih)^T + bias ------------
// M=65536 (BM=128), N=4096 (BN=128), K=448 (7 tiles of 64), 2 A-terms share B.
__global__ __launch_bounds__(256)
void xg_gemm() {
    extern __shared__ char smem[];
    const uint32_t sb = s2u(smem);
    const int tid = threadIdx.x;
    const int lane = tid & 31, wid = tid >> 5;
    const int wm = wid & 1, wn = wid >> 1;      // warp tile 64x32
    const int n0 = blockIdx.x * 128;
    const int m0 = blockIdx.y * 128;

    // cp.async dst offsets (within stage), 4 chunks per thread per region
    uint32_t dst[4];
#pragma unroll
    for (int i = 0; i < 4; i++) {
        int ch = tid + i * 256;                 // 0..1023 = 128 rows x 8 cc
        dst[i] = SW128(((ch >> 3) << 7) + (ch & 7) * 16);
    }

    uint32_t offAh[4][4], offB[2][4];
#pragma unroll
    for (int mf = 0; mf < 4; mf++)
#pragma unroll
        for (int k = 0; k < 4; k++)
            offAh[mf][k] = SW128((wm * 64 + mf * 16 + (lane & 15)) * 128 + k * 32 + (lane >> 4) * 16);
#pragma unroll
    for (int bj = 0; bj < 2; bj++)
#pragma unroll
        for (int k = 0; k < 4; k++)
            offB[bj][k] = 32768 + SW128((wn * 32 + bj * 16 + (lane & 15)) * 128 + k * 32 + (lane >> 4) * 16);

    float acc[4][4][4];
#pragma unroll
    for (int i = 0; i < 4; i++)
#pragma unroll
        for (int j = 0; j < 4; j++)
#pragma unroll
            for (int q = 0; q < 4; q++) acc[i][j][q] = 0.f;

    auto load_tile = [&](int j) {
        const uint32_t base = sb + (j % 3) * XST;
        const int kc = j * 64;
#pragma unroll
        for (int i = 0; i < 4; i++) {
            int ch = tid + i * 256; int row = ch >> 3, cc = ch & 7;
            cp16(base + dst[i], g_xh + (size_t)(m0 + row) * KX + kc + cc * 8);
            cp16(base + 16384 + dst[i], g_xl + (size_t)(m0 + row) * KX + kc + cc * 8);
            cp16(base + 32768 + dst[i], g_Wx + (size_t)(n0 + row) * KX + kc + cc * 8);
        }
        cp_commit();
    };

    load_tile(0); load_tile(1); load_tile(2);
    const int NTX = KX / 64;                    // 7
    for (int kt = 0; kt < NTX; kt++) {
        cp_wait2();
        __syncthreads();
        const uint32_t base = sb + (kt % 3) * XST;
#pragma unroll
        for (int k16 = 0; k16 < 4; k16++) {
            uint32_t b0[4], b1[4];
            ldsm4(b0[0], b0[1], b0[2], b0[3], base + offB[0][k16]);
            ldsm4(b1[0], b1[1], b1[2], b1[3], base + offB[1][k16]);
#pragma unroll
            for (int mf = 0; mf < 4; mf++) {
                uint32_t ah[4], al[4];
                ldsm4(ah[0], ah[1], ah[2], ah[3], base + offAh[mf][k16]);
                mma16816(acc[mf][0], ah, b0[0], b0[2]);
                mma16816(acc[mf][1], ah, b0[1], b0[3]);
                mma16816(acc[mf][2], ah, b1[0], b1[2]);
                mma16816(acc[mf][3], ah, b1[1], b1[3]);
                ldsm4(al[0], al[1], al[2], al[3], base + 16384 + offAh[mf][k16]);
                mma16816(acc[mf][0], al, b0[0], b0[2]);
                mma16816(acc[mf][1], al, b0[1], b0[3]);
                mma16816(acc[mf][2], al, b1[0], b1[2]);
                mma16816(acc[mf][3], al, b1[1], b1[3]);
            }
        }
        __syncthreads();
        if (kt + 3 < NTX) load_tile(kt + 3); else cp_commit();
    }

    // epilogue: stage 128x128 through smem, add bias
    float* sg = (float*)smem;                   // [128][132] = 67.5 KB
#pragma unroll
    for (int mf = 0; mf < 4; mf++)
#pragma unroll
        for (int nj = 0; nj < 4; nj++) {
            int row = wm * 64 + mf * 16 + (lane >> 2);
            int col = wn * 32 + nj * 8 + (lane & 3) * 2;
            sg[row * 132 + col]       = acc[mf][nj][0];
            sg[row * 132 + col + 1]   = acc[mf][nj][1];
            sg[(row + 8) * 132 + col]     = acc[mf][nj][2];
            sg[(row + 8) * 132 + col + 1] = acc[mf][nj][3];
        }
    __syncthreads();
#pragma unroll
    for (int i = 0; i < 16; i++) {
        int idx = tid + i * 256;                // 128 rows x 32 float4
        int c4 = idx & 31, row = idx >> 5;
        float4 v = *(float4*)&sg[row * 132 + c4 * 4];
        float4 bz = *(const float4*)&g_bias[n0 + c4 * 4];
        v.x += bz.x; v.y += bz.y; v.z += bz.z; v.w += bz.w;
        *(float4*)(g_xg + (size_t)(m0 + row) * G4 + n0 + c4 * 4) = v;
    }
}

// ---------------- persistent recurrence kernel ----------------------------------
__global__ __launch_bounds__(256)
void persist_kernel() {
    extern __shared__ char smem[];
    const uint32_t sb = s2u(smem);
    const int tid = threadIdx.x;
    const int lane = tid & 31, wid = tid >> 5;
    const int wm = wid & 1, wn = wid >> 1;
    const int n0 = blockIdx.x * BN;
    const int m0 = blockIdx.y * BM;

    uint32_t dAh[2], dAl[2], dB[4];
#pragma unroll
    for (int i = 0; i < 2; i++) {
        int ch = tid + i * 256;
        uint32_t o = SW128(((ch >> 3) << 7) + (ch & 7) * 16);
        dAh[i] = o; dAl[i] = 8192 + o;
    }
#pragma unroll
    for (int i = 0; i < 4; i++) {
        int ch = tid + i * 256;
        dB[i] = 16384 + SW128(((ch >> 3) << 7) + (ch & 7) * 16);
    }

    uint32_t offAh[2][4], offAl[2][4], offB[2][4];
#pragma unroll
    for (int mi = 0; mi < 2; mi++)
#pragma unroll
        for (int k = 0; k < 4; k++) {
            uint32_t o = SW128((wm * 32 + mi * 16 + (lane & 15)) * 128 + k * 32 + (lane >> 4) * 16);
            offAh[mi][k] = o; offAl[mi][k] = 8192 + o;
        }
#pragma unroll
    for (int bj = 0; bj < 2; bj++)
#pragma unroll
        for (int k = 0; k < 4; k++)
            offB[bj][k] = 16384 + SW128((wn * 32 + bj * 16 + (lane & 15)) * 128 + k * 32 + (lane >> 4) * 16);

    auto loadB = [&](int j) {                   // W tile: h-independent
        const uint32_t base = sb + (j & 3) * PST;
        const int kc = j * 64;
#pragma unroll
        for (int i = 0; i < 4; i++) {
            int ch = tid + i * 256; int row = ch >> 3, cc = ch & 7;
            cp16(base + dB[i], g_W + (size_t)(n0 + row) * Hn + kc + cc * 8);
        }
        cp_commit();
    };

    // prologue: W tiles 0..2 in flight before step loop
    loadB(0); loadB(1); loadB(2);

    for (int t = 0; t < Tn; t++) {
        const int p = t & 1;
        const __half* __restrict__ hhi = g_hhi[p];
        const __half* __restrict__ hlo = g_hlo[p];

        auto loadA = [&](int j) {
            const uint32_t base = sb + (j & 3) * PST;
            const int kc = j * 64;
#pragma unroll
            for (int i = 0; i < 2; i++) {
                int ch = tid + i * 256; int row = ch >> 3, cc = ch & 7;
                cp16(base + dAh[i], hhi + (size_t)(m0 + row) * Hn + kc + cc * 8);
                cp16(base + dAl[i], hlo + (size_t)(m0 + row) * Hn + kc + cc * 8);
            }
            cp_commit();
        };
        auto load_tile = [&](int j) {
            const uint32_t base = sb + (j & 3) * PST;
            const int kc = j * 64;
#pragma unroll
            for (int i = 0; i < 2; i++) {
                int ch = tid + i * 256; int row = ch >> 3, cc = ch & 7;
                cp16(base + dAh[i], hhi + (size_t)(m0 + row) * Hn + kc + cc * 8);
                cp16(base + dAl[i], hlo + (size_t)(m0 + row) * Hn + kc + cc * 8);
            }
#pragma unroll
            for (int i = 0; i < 4; i++) {
                int ch = tid + i * 256; int row = ch >> 3, cc = ch & 7;
                cp16(base + dB[i], g_W + (size_t)(n0 + row) * Hn + kc + cc * 8);
            }
            cp_commit();
        };

        float acc[2][4][4];
#pragma unroll
        for (int i = 0; i < 2; i++)
#pragma unroll
            for (int j = 0; j < 4; j++)
#pragma unroll
                for (int q = 0; q < 4; q++) acc[i][j][q] = 0.f;

        loadA(0); loadA(1); loadA(2);           // B for 0..2 already in flight
        for (int kt = 0; kt < NT; kt++) {
            cp_wait2();
            __syncthreads();
            const uint32_t base = sb + (kt & 3) * PST;
#pragma unroll
            for (int k16 = 0; k16 < 4; k16++) {
                uint32_t ah[2][4], al[2][4], b[2][4];
                ldsm4(ah[0][0], ah[0][1], ah[0][2], ah[0][3], base + offAh[0][k16]);
                ldsm4(ah[1][0], ah[1][1], ah[1][2], ah[1][3], base + offAh[1][k16]);
                ldsm4(al[0][0], al[0][1], al[0][2], al[0][3], base + offAl[0][k16]);
                ldsm4(al[1][0], al[1][1], al[1][2], al[1][3], base + offAl[1][k16]);
                ldsm4(b[0][0], b[0][1], b[0][2], b[0][3], base + offB[0][k16]);
                ldsm4(b[1][0], b[1][1], b[1][2], b[1][3], base + offB[1][k16]);
#pragma unroll
                for (int mi = 0; mi < 2; mi++) {
                    mma16816(acc[mi][0], ah[mi], b[0][0], b[0][2]);
                    mma16816(acc[mi][1], ah[mi], b[0][1], b[0][3]);
                    mma16816(acc[mi][2], ah[mi], b[1][0], b[1][2]);
                    mma16816(acc[mi][3], ah[mi], b[1][1], b[1][3]);
                    mma16816(acc[mi][0], al[mi], b[0][0], b[0][2]);
                    mma16816(acc[mi][1], al[mi], b[0][1], b[0][3]);
                    mma16816(acc[mi][2], al[mi], b[1][0], b[1][2]);
                    mma16816(acc[mi][3], al[mi], b[1][1], b[1][3]);
                }
            }
            if (kt + 3 < NT) load_tile(kt + 3); else cp_commit();
        }
        __syncthreads();

        // ---- epilogue ----
        float* sg = (float*)smem;               // [64][132]
#pragma unroll
        for (int mi = 0; mi < 2; mi++)
#pragma unroll
            for (int nj = 0; nj < 4; nj++) {
                int row = wm * 32 + mi * 16 + (lane >> 2);
                int col = wn * 32 + nj * 8 + (lane & 3) * 2;
                sg[row * 132 + col]       = acc[mi][nj][0];
                sg[row * 132 + col + 1]   = acc[mi][nj][1];
                sg[(row + 8) * 132 + col]     = acc[mi][nj][2];
                sg[(row + 8) * 132 + col + 1] = acc[mi][nj][3];
            }
        __syncthreads();

        __half* __restrict__ ohi = g_hhi[p ^ 1];
        __half* __restrict__ olo = g_hlo[p ^ 1];
#pragma unroll
        for (int i = 0; i < 8; i++) {
            int idx = tid + i * 256;
            int u = idx & 31, row = idx >> 5;
            float4 gv4 = *(float4*)&sg[row * 132 + u * 4];
            float4 xv = *(const float4*)(g_xg + ((size_t)t * Bn + m0 + row) * G4 + n0 + u * 4);
            float iv = sigf(gv4.x + xv.x);
            float fv = sigf(gv4.y + xv.y);
            float gg = tanhf(gv4.z + xv.z);
            float ov = sigf(gv4.w + xv.w);
            int ci = (m0 + row) * Hn + (n0 >> 2) + u;
            float cn = fv * g_c[ci] + iv * gg;
            g_c[ci] = cn;
            float h = ov * tanhf(cn);
            __half hi = __float2half_rn(h);
            ohi[ci] = hi;
            olo[ci] = __float2half_rn(h - __half2float(hi));
        }
        __syncthreads();                        // sg reads done before B-prefetch clobbers stage0

        // prefetch next step's W tiles during barrier wait
        loadB(0); loadB(1); loadB(2);

        __threadfence();
        __syncthreads();
        if (tid == 0) {
            atomicAdd(&g_bar, 1);
            while (*((volatile int*)&g_bar) < NCTA * (t + 1)) { }
            __threadfence();
        }
        __syncthreads();
    }
}

// ---------------- MLP head ------------------------------------------------------
__global__ __launch_bounds__(256)
void mlp_kernel(const float* __restrict__ W1, const float* __restrict__ b1,
                const float* __restrict__ W2, const float* __restrict__ b2,
                float* __restrict__ out) {
    __shared__ __align__(16) float hs[Hn];
    __shared__ float hid[512];
    __shared__ float red[256];
    int bb = blockIdx.x, tid = threadIdx.x;
    for (int i = tid; i < Hn; i += 256)
        hs[i] = __half2float(g_hhi[0][bb * Hn + i]) + __half2float(g_hlo[0][bb * Hn + i]);
    __syncthreads();
    for (int j = tid; j < 512; j += 256) {
        const float4* w = (const float4*)(W1 + j * Hn);
        float s = 0.f;
#pragma unroll 8
        for (int k = 0; k < Hn / 4; k++) {
            float4 w4 = w[k];
            s += w4.x * hs[4 * k] + w4.y * hs[4 * k + 1] + w4.z * hs[4 * k + 2] + w4.w * hs[4 * k + 3];
        }
        s += b1[j];
        hid[j] = s > 0.f ? s : 0.f;
    }
    __syncthreads();
    red[tid] = hid[tid] * W2[tid] + hid[tid + 256] * W2[tid + 256];
    __syncthreads();
    for (int s = 128; s > 0; s >>= 1) {
        if (tid < s) red[tid] += red[tid + s];
        __syncthreads();
    }
    if (tid == 0) out[bb] = red[0] + b2[0];
}

// ---------------- launch --------------------------------------------------------
extern "C" void kernel_launch(void* const* d_in, const int* in_sizes, int n_in,
                              void* d_out, int out_size) {
    const float* x_text   = (const float*)d_in[0];
    const float* x_audio  = (const float*)d_in[1];
    const float* x_vision = (const float*)d_in[2];
    const float* W_ih     = (const float*)d_in[3];
    const float* W_hh     = (const float*)d_in[4];
    const float* b_ih     = (const float*)d_in[5];
    const float* b_hh     = (const float*)d_in[6];
    const float* W1       = (const float*)d_in[7];
    const float* b1       = (const float*)d_in[8];
    const float* W2       = (const float*)d_in[9];
    const float* b2       = (const float*)d_in[10];
    float* out = (float*)d_out;

    cudaFuncSetAttribute(xg_gemm, cudaFuncAttributeMaxDynamicSharedMemorySize, XSMEM);
    cudaFuncSetAttribute(persist_kernel, cudaFuncAttributeMaxDynamicSharedMemorySize, PSMEM);

    {
        size_t n = (size_t)MXG * KX;
        prep_x<<<(unsigned)((n + 255) / 256), 256>>>(x_text, x_audio, x_vision);
    }
    {
        size_t n = (size_t)G4 * Hn;
        prep_w<<<(unsigned)((n + 255) / 256), 256>>>(W_hh);
    }
    {
        size_t n = (size_t)G4 * KX;
        prep_wx<<<(unsigned)((n + 255) / 256), 256>>>(W_ih);
    }
    prep_bias<<<G4 / 256, 256>>>(b_ih, b_hh);
    init_state<<<(Bn * Hn + 255) / 256, 256>>>();

    xg_gemm<<<dim3(G4 / 128, MXG / 128), 256, XSMEM>>>();

    persist_kernel<<<dim3(G4 / BN, Bn / BM), 256, PSMEM>>>();

    mlp_kernel<<<Bn, 256>>>(W1, b1, W2, b2, out);
}

// round 8
// speedup vs baseline: 1.5416x; 1.5416x over previous
#include <cuda_runtime.h>
#include <cuda_fp16.h>
#include <cstdint>

#define Bn 256
#define Tn 256
#define Hn 1024
#define G4 4096
#define Dn 409
#define KX 448            // D padded to 7*64
#define MXG 65536         // B*T
#define BM 64
#define BN 128
#define NT 16             // k-tiles of 64 over K=1024
#define NCTA 128

// ---------------- device scratch ----------------------------------------------
__device__ __align__(16) __half g_W[(size_t)G4 * Hn];       // 8 MB fp16(Whh) gate-interleaved
__device__ __align__(16) __half g_Wx[(size_t)G4 * KX];      // 3.7 MB fp16(Wih)
__device__ __align__(16) __half g_xh[(size_t)MXG * KX];     // 58.7 MB x hi
__device__ __align__(16) __half g_xl[(size_t)MXG * KX];     // 58.7 MB x lo
__device__ float g_xg[(size_t)MXG * G4];                    // 1 GiB
__device__ __align__(16) __half g_hhi[2][Bn * Hn];
__device__ __align__(16) __half g_hlo[2][Bn * Hn];
__device__ float g_c[Bn * Hn];
__device__ float g_bias[G4];
__device__ int g_bar;

// ---------------- PTX helpers ---------------------------------------------------
__device__ __forceinline__ uint32_t s2u(const void* p) {
    uint32_t a;
    asm("{ .reg .u64 t; cvta.to.shared.u64 t, %1; cvt.u32.u64 %0, t; }" : "=r"(a) : "l"(p));
    return a;
}
__device__ __forceinline__ void cp16(uint32_t dst, const void* src) {
    asm volatile("cp.async.cg.shared.global [%0], [%1], 16;" :: "r"(dst), "l"(src));
}
__device__ __forceinline__ void cp_commit() { asm volatile("cp.async.commit_group;"); }
__device__ __forceinline__ void cp_wait2() { asm volatile("cp.async.wait_group 2;" ::: "memory"); }

__device__ __forceinline__ void ldsm4(uint32_t& r0, uint32_t& r1, uint32_t& r2, uint32_t& r3,
                                      uint32_t addr) {
    asm volatile("ldmatrix.sync.aligned.m8n8.x4.shared.b16 {%0,%1,%2,%3}, [%4];"
                 : "=r"(r0), "=r"(r1), "=r"(r2), "=r"(r3) : "r"(addr));
}
__device__ __forceinline__ void mma16816(float* d, const uint32_t* a, uint32_t b0, uint32_t b1) {
    asm volatile(
        "mma.sync.aligned.m16n8k16.row.col.f32.f16.f16.f32 "
        "{%0,%1,%2,%3}, {%4,%5,%6,%7}, {%8,%9}, {%0,%1,%2,%3};"
        : "+f"(d[0]), "+f"(d[1]), "+f"(d[2]), "+f"(d[3])
        : "r"(a[0]), "r"(a[1]), "r"(a[2]), "r"(a[3]), "r"(b0), "r"(b1));
}

#define SW128(o) ((o) ^ (((o) >> 3) & 0x70))
// stage layout (both gemms): A_hi 8KB @0, A_lo 8KB @8192, B 16KB @16384 -> 32KB
#define PST 32768
#define PSMEM (4 * PST)     // persist: 4 stages
#define XSMEM (3 * PST)     // xg: 3 stages = 96KB -> 2 CTAs/SM

__device__ __forceinline__ float sigf(float x) { return 1.f / (1.f + expf(-x)); }

// ---------------- prep kernels --------------------------------------------------
__global__ void prep_x(const float* __restrict__ xt, const float* __restrict__ xa,
                       const float* __restrict__ xv) {
    size_t idx = (size_t)blockIdx.x * blockDim.x + threadIdx.x;
    if (idx >= (size_t)MXG * KX) return;
    int c = idx % KX;
    int r = idx / KX;             // r = t*256 + b
    int t = r >> 8, b = r & 255;
    int bt = b * Tn + t;
    float v = 0.f;
    if (c < 300)       v = xt[(size_t)bt * 300 + c];
    else if (c < 374)  v = xa[(size_t)bt * 74 + (c - 300)];
    else if (c < 409)  v = xv[(size_t)bt * 35 + (c - 374)];
    __half hi = __float2half_rn(v);
    g_xh[idx] = hi;
    g_xl[idx] = __float2half_rn(v - __half2float(hi));
}

__global__ void prep_w(const float* __restrict__ Whh) {
    size_t idx = (size_t)blockIdx.x * blockDim.x + threadIdx.x;
    if (idx >= (size_t)G4 * Hn) return;
    int c = idx % Hn;
    int rp = idx / Hn;
    int k = rp >> 2, g = rp & 3;
    g_W[idx] = __float2half_rn(Whh[(size_t)(g * Hn + k) * Hn + c]);
}

__global__ void prep_wx(const float* __restrict__ Wih) {
    size_t idx = (size_t)blockIdx.x * blockDim.x + threadIdx.x;
    if (idx >= (size_t)G4 * KX) return;
    int c = idx % KX;
    int rp = idx / KX;
    int k = rp >> 2, g = rp & 3;
    float v = (c < Dn) ? Wih[(size_t)(g * Hn + k) * Dn + c] : 0.f;
    g_Wx[idx] = __float2half_rn(v);
}

__global__ void prep_bias(const float* __restrict__ bih, const float* __restrict__ bhh) {
    int o = blockIdx.x * blockDim.x + threadIdx.x;
    if (o >= G4) return;
    int k = o >> 2, g = o & 3;
    g_bias[o] = bih[g * Hn + k] + bhh[g * Hn + k];
}

__global__ void init_state() {
    int idx = blockIdx.x * blockDim.x + threadIdx.x;
    if (idx == 0) g_bar = 0;
    if (idx < Bn * Hn) {
        g_hhi[0][idx] = __float2half_rn(0.f);
        g_hlo[0][idx] = __float2half_rn(0.f);
        g_c[idx] = 0.f;
    }
}

// ---------------- xg GEMM: g_xg = (x_hi + x_lo) @ fp16(Wih)^T + bias ------------
// M=65536 (BM=64), N=4096 (BN=128), K=448 (7 tiles of 64), 2 A-terms share B.
// Same stage/inner-loop structure as the proven persist kernel; 96KB smem -> 2 CTA/SM.
__global__ __launch_bounds__(256)
void xg_gemm() {
    extern __shared__ char smem[];
    const uint32_t sb = s2u(smem);
    const int tid = threadIdx.x;
    const int lane = tid & 31, wid = tid >> 5;
    const int wm = wid & 1, wn = wid >> 1;
    const int n0 = blockIdx.x * BN;
    const int m0 = blockIdx.y * BM;

    uint32_t dAh[2], dAl[2], dB[4];
#pragma unroll
    for (int i = 0; i < 2; i++) {
        int ch = tid + i * 256;
        uint32_t o = SW128(((ch >> 3) << 7) + (ch & 7) * 16);
        dAh[i] = o; dAl[i] = 8192 + o;
    }
#pragma unroll
    for (int i = 0; i < 4; i++) {
        int ch = tid + i * 256;
        dB[i] = 16384 + SW128(((ch >> 3) << 7) + (ch & 7) * 16);
    }

    uint32_t offAh[2][4], offAl[2][4], offB[2][4];
#pragma unroll
    for (int mi = 0; mi < 2; mi++)
#pragma unroll
        for (int k = 0; k < 4; k++) {
            uint32_t o = SW128((wm * 32 + mi * 16 + (lane & 15)) * 128 + k * 32 + (lane >> 4) * 16);
            offAh[mi][k] = o; offAl[mi][k] = 8192 + o;
        }
#pragma unroll
    for (int bj = 0; bj < 2; bj++)
#pragma unroll
        for (int k = 0; k < 4; k++)
            offB[bj][k] = 16384 + SW128((wn * 32 + bj * 16 + (lane & 15)) * 128 + k * 32 + (lane >> 4) * 16);

    float acc[2][4][4];
#pragma unroll
    for (int i = 0; i < 2; i++)
#pragma unroll
        for (int j = 0; j < 4; j++)
#pragma unroll
            for (int q = 0; q < 4; q++) acc[i][j][q] = 0.f;

    auto load_tile = [&](int j) {
        const uint32_t base = sb + (j % 3) * PST;
        const int kc = j * 64;
#pragma unroll
        for (int i = 0; i < 2; i++) {
            int ch = tid + i * 256; int row = ch >> 3, cc = ch & 7;
            cp16(base + dAh[i], g_xh + (size_t)(m0 + row) * KX + kc + cc * 8);
            cp16(base + dAl[i], g_xl + (size_t)(m0 + row) * KX + kc + cc * 8);
        }
#pragma unroll
        for (int i = 0; i < 4; i++) {
            int ch = tid + i * 256; int row = ch >> 3, cc = ch & 7;
            cp16(base + dB[i], g_Wx + (size_t)(n0 + row) * KX + kc + cc * 8);
        }
        cp_commit();
    };

    load_tile(0); load_tile(1); load_tile(2);
    const int NTX = KX / 64;                    // 7
    for (int kt = 0; kt < NTX; kt++) {
        cp_wait2();
        __syncthreads();
        const uint32_t base = sb + (kt % 3) * PST;
#pragma unroll
        for (int k16 = 0; k16 < 4; k16++) {
            uint32_t ah[2][4], al[2][4], b[2][4];
            ldsm4(ah[0][0], ah[0][1], ah[0][2], ah[0][3], base + offAh[0][k16]);
            ldsm4(ah[1][0], ah[1][1], ah[1][2], ah[1][3], base + offAh[1][k16]);
            ldsm4(al[0][0], al[0][1], al[0][2], al[0][3], base + offAl[0][k16]);
            ldsm4(al[1][0], al[1][1], al[1][2], al[1][3], base + offAl[1][k16]);
            ldsm4(b[0][0], b[0][1], b[0][2], b[0][3], base + offB[0][k16]);
            ldsm4(b[1][0], b[1][1], b[1][2], b[1][3], base + offB[1][k16]);
#pragma unroll
            for (int mi = 0; mi < 2; mi++) {
                mma16816(acc[mi][0], ah[mi], b[0][0], b[0][2]);
                mma16816(acc[mi][1], ah[mi], b[0][1], b[0][3]);
                mma16816(acc[mi][2], ah[mi], b[1][0], b[1][2]);
                mma16816(acc[mi][3], ah[mi], b[1][1], b[1][3]);
                mma16816(acc[mi][0], al[mi], b[0][0], b[0][2]);
                mma16816(acc[mi][1], al[mi], b[0][1], b[0][3]);
                mma16816(acc[mi][2], al[mi], b[1][0], b[1][2]);
                mma16816(acc[mi][3], al[mi], b[1][1], b[1][3]);
            }
        }
        if (kt + 3 < NTX) load_tile(kt + 3); else cp_commit();
    }
    __syncthreads();                            // all ldsm done before sg overwrite

    // epilogue: stage 64x128 through smem, add bias, store fp32
    float* sg = (float*)smem;                   // [64][132]
#pragma unroll
    for (int mi = 0; mi < 2; mi++)
#pragma unroll
        for (int nj = 0; nj < 4; nj++) {
            int row = wm * 32 + mi * 16 + (lane >> 2);
            int col = wn * 32 + nj * 8 + (lane & 3) * 2;
            sg[row * 132 + col]       = acc[mi][nj][0];
            sg[row * 132 + col + 1]   = acc[mi][nj][1];
            sg[(row + 8) * 132 + col]     = acc[mi][nj][2];
            sg[(row + 8) * 132 + col + 1] = acc[mi][nj][3];
        }
    __syncthreads();
#pragma unroll
    for (int i = 0; i < 8; i++) {
        int idx = tid + i * 256;
        int c4 = idx & 31, row = idx >> 5;
        float4 v = *(float4*)&sg[row * 132 + c4 * 4];
        float4 bz = *(const float4*)&g_bias[n0 + c4 * 4];
        v.x += bz.x; v.y += bz.y; v.z += bz.z; v.w += bz.w;
        *(float4*)(g_xg + (size_t)(m0 + row) * G4 + n0 + c4 * 4) = v;
    }
}

// ---------------- persistent recurrence kernel (exact R6) -----------------------
__global__ __launch_bounds__(256)
void persist_kernel() {
    extern __shared__ char smem[];
    const uint32_t sb = s2u(smem);
    const int tid = threadIdx.x;
    const int lane = tid & 31, wid = tid >> 5;
    const int wm = wid & 1, wn = wid >> 1;
    const int n0 = blockIdx.x * BN;
    const int m0 = blockIdx.y * BM;

    uint32_t dAh[2], dAl[2], dB[4];
#pragma unroll
    for (int i = 0; i < 2; i++) {
        int ch = tid + i * 256;
        uint32_t o = SW128(((ch >> 3) << 7) + (ch & 7) * 16);
        dAh[i] = o; dAl[i] = 8192 + o;
    }
#pragma unroll
    for (int i = 0; i < 4; i++) {
        int ch = tid + i * 256;
        dB[i] = 16384 + SW128(((ch >> 3) << 7) + (ch & 7) * 16);
    }

    uint32_t offAh[2][4], offAl[2][4], offB[2][4];
#pragma unroll
    for (int mi = 0; mi < 2; mi++)
#pragma unroll
        for (int k = 0; k < 4; k++) {
            uint32_t o = SW128((wm * 32 + mi * 16 + (lane & 15)) * 128 + k * 32 + (lane >> 4) * 16);
            offAh[mi][k] = o; offAl[mi][k] = 8192 + o;
        }
#pragma unroll
    for (int bj = 0; bj < 2; bj++)
#pragma unroll
        for (int k = 0; k < 4; k++)
            offB[bj][k] = 16384 + SW128((wn * 32 + bj * 16 + (lane & 15)) * 128 + k * 32 + (lane >> 4) * 16);

    for (int t = 0; t < Tn; t++) {
        const int p = t & 1;
        const __half* __restrict__ hhi = g_hhi[p];
        const __half* __restrict__ hlo = g_hlo[p];

        auto load_tile = [&](int j) {
            const uint32_t base = sb + (j & 3) * PST;
            const int kc = j * 64;
#pragma unroll
            for (int i = 0; i < 2; i++) {
                int ch = tid + i * 256; int row = ch >> 3, cc = ch & 7;
                cp16(base + dAh[i], hhi + (size_t)(m0 + row) * Hn + kc + cc * 8);
                cp16(base + dAl[i], hlo + (size_t)(m0 + row) * Hn + kc + cc * 8);
            }
#pragma unroll
            for (int i = 0; i < 4; i++) {
                int ch = tid + i * 256; int row = ch >> 3, cc = ch & 7;
                cp16(base + dB[i], g_W + (size_t)(n0 + row) * Hn + kc + cc * 8);
            }
            cp_commit();
        };

        float acc[2][4][4];
#pragma unroll
        for (int i = 0; i < 2; i++)
#pragma unroll
            for (int j = 0; j < 4; j++)
#pragma unroll
                for (int q = 0; q < 4; q++) acc[i][j][q] = 0.f;

        load_tile(0); load_tile(1); load_tile(2);
        for (int kt = 0; kt < NT; kt++) {
            cp_wait2();
            __syncthreads();
            const uint32_t base = sb + (kt & 3) * PST;
#pragma unroll
            for (int k16 = 0; k16 < 4; k16++) {
                uint32_t ah[2][4], al[2][4], b[2][4];
                ldsm4(ah[0][0], ah[0][1], ah[0][2], ah[0][3], base + offAh[0][k16]);
                ldsm4(ah[1][0], ah[1][1], ah[1][2], ah[1][3], base + offAh[1][k16]);
                ldsm4(al[0][0], al[0][1], al[0][2], al[0][3], base + offAl[0][k16]);
                ldsm4(al[1][0], al[1][1], al[1][2], al[1][3], base + offAl[1][k16]);
                ldsm4(b[0][0], b[0][1], b[0][2], b[0][3], base + offB[0][k16]);
                ldsm4(b[1][0], b[1][1], b[1][2], b[1][3], base + offB[1][k16]);
#pragma unroll
                for (int mi = 0; mi < 2; mi++) {
                    mma16816(acc[mi][0], ah[mi], b[0][0], b[0][2]);
                    mma16816(acc[mi][1], ah[mi], b[0][1], b[0][3]);
                    mma16816(acc[mi][2], ah[mi], b[1][0], b[1][2]);
                    mma16816(acc[mi][3], ah[mi], b[1][1], b[1][3]);
                    mma16816(acc[mi][0], al[mi], b[0][0], b[0][2]);
                    mma16816(acc[mi][1], al[mi], b[0][1], b[0][3]);
                    mma16816(acc[mi][2], al[mi], b[1][0], b[1][2]);
                    mma16816(acc[mi][3], al[mi], b[1][1], b[1][3]);
                }
            }
            if (kt + 3 < NT) load_tile(kt + 3); else cp_commit();
        }
        __syncthreads();

        // ---- epilogue ----
        float* sg = (float*)smem;               // [64][132]
#pragma unroll
        for (int mi = 0; mi < 2; mi++)
#pragma unroll
            for (int nj = 0; nj < 4; nj++) {
                int row = wm * 32 + mi * 16 + (lane >> 2);
                int col = wn * 32 + nj * 8 + (lane & 3) * 2;
                sg[row * 132 + col]       = acc[mi][nj][0];
                sg[row * 132 + col + 1]   = acc[mi][nj][1];
                sg[(row + 8) * 132 + col]     = acc[mi][nj][2];
                sg[(row + 8) * 132 + col + 1] = acc[mi][nj][3];
            }
        __syncthreads();

        __half* __restrict__ ohi = g_hhi[p ^ 1];
        __half* __restrict__ olo = g_hlo[p ^ 1];
#pragma unroll
        for (int i = 0; i < 8; i++) {
            int idx = tid + i * 256;
            int u = idx & 31, row = idx >> 5;
            float4 gv4 = *(float4*)&sg[row * 132 + u * 4];
            float4 xv = *(const float4*)(g_xg + ((size_t)t * Bn + m0 + row) * G4 + n0 + u * 4);
            float iv = sigf(gv4.x + xv.x);
            float fv = sigf(gv4.y + xv.y);
            float gg = tanhf(gv4.z + xv.z);
            float ov = sigf(gv4.w + xv.w);
            int ci = (m0 + row) * Hn + (n0 >> 2) + u;
            float cn = fv * g_c[ci] + iv * gg;
            g_c[ci] = cn;
            float h = ov * tanhf(cn);
            __half hi = __float2half_rn(h);
            ohi[ci] = hi;
            olo[ci] = __float2half_rn(h - __half2float(hi));
        }

        // ---- global barrier ----
        __threadfence();
        __syncthreads();
        if (tid == 0) {
            atomicAdd(&g_bar, 1);
            while (*((volatile int*)&g_bar) < NCTA * (t + 1)) { }
            __threadfence();
        }
        __syncthreads();
    }
}

// ---------------- MLP head ------------------------------------------------------
__global__ __launch_bounds__(256)
void mlp_kernel(const float* __restrict__ W1, const float* __restrict__ b1,
                const float* __restrict__ W2, const float* __restrict__ b2,
                float* __restrict__ out) {
    __shared__ __align__(16) float hs[Hn];
    __shared__ float hid[512];
    __shared__ float red[256];
    int bb = blockIdx.x, tid = threadIdx.x;
    for (int i = tid; i < Hn; i += 256)
        hs[i] = __half2float(g_hhi[0][bb * Hn + i]) + __half2float(g_hlo[0][bb * Hn + i]);
    __syncthreads();
    for (int j = tid; j < 512; j += 256) {
        const float4* w = (const float4*)(W1 + j * Hn);
        float s = 0.f;
#pragma unroll 8
        for (int k = 0; k < Hn / 4; k++) {
            float4 w4 = w[k];
            s += w4.x * hs[4 * k] + w4.y * hs[4 * k + 1] + w4.z * hs[4 * k + 2] + w4.w * hs[4 * k + 3];
        }
        s += b1[j];
        hid[j] = s > 0.f ? s : 0.f;
    }
    __syncthreads();
    red[tid] = hid[tid] * W2[tid] + hid[tid + 256] * W2[tid + 256];
    __syncthreads();
    for (int s = 128; s > 0; s >>= 1) {
        if (tid < s) red[tid] += red[tid + s];
        __syncthreads();
    }
    if (tid == 0) out[bb] = red[0] + b2[0];
}

// ---------------- launch --------------------------------------------------------
extern "C" void kernel_launch(void* const* d_in, const int* in_sizes, int n_in,
                              void* d_out, int out_size) {
    const float* x_text   = (const float*)d_in[0];
    const float* x_audio  = (const float*)d_in[1];
    const float* x_vision = (const float*)d_in[2];
    const float* W_ih     = (const float*)d_in[3];
    const float* W_hh     = (const float*)d_in[4];
    const float* b_ih     = (const float*)d_in[5];
    const float* b_hh     = (const float*)d_in[6];
    const float* W1       = (const float*)d_in[7];
    const float* b1       = (const float*)d_in[8];
    const float* W2       = (const float*)d_in[9];
    const float* b2       = (const float*)d_in[10];
    float* out = (float*)d_out;

    cudaFuncSetAttribute(xg_gemm, cudaFuncAttributeMaxDynamicSharedMemorySize, XSMEM);
    cudaFuncSetAttribute(persist_kernel, cudaFuncAttributeMaxDynamicSharedMemorySize, PSMEM);

    // Order chosen so xg_gemm is the 4th launch (= the one ncu -s 5 -c 1 captures).
    {
        size_t n = (size_t)MXG * KX;
        prep_x<<<(unsigned)((n + 255) / 256), 256>>>(x_text, x_audio, x_vision);
    }
    {
        size_t n = (size_t)G4 * KX;
        prep_wx<<<(unsigned)((n + 255) / 256), 256>>>(W_ih);
    }
    prep_bias<<<G4 / 256, 256>>>(b_ih, b_hh);

    xg_gemm<<<dim3(G4 / BN, MXG / BM), 256, XSMEM>>>();

    {
        size_t n = (size_t)G4 * Hn;
        prep_w<<<(unsigned)((n + 255) / 256), 256>>>(W_hh);
    }
    init_state<<<(Bn * Hn + 255) / 256, 256>>>();

    persist_kernel<<<dim3(G4 / BN, Bn / BM), 256, PSMEM>>>();

    mlp_kernel<<<Bn, 256>>>(W1, b1, W2, b2, out);
}